// round 9
// baseline (speedup 1.0000x reference)
#include <cuda_runtime.h>
#include <cstdint>

// OrbitalFeatureGNN: antisymmetrize(gnn, tmp_axis=-4) where tmp_axis is the
// S axis (S=2). gnn acts independently and identically on each S slice (all
// inter-element coupling is over the ion axis N; weights are S-independent),
// so gnn commutes with flip along S:
//   0.5 * (gnn(x) - flip(gnn(flip(x)))) = 0.5 * (gnn(x) - gnn(x)) = 0
// exactly (bitwise). Verified rel_err == 0.0 in R1/R2/R4/R5/R7.
//
// R8: revert to the R5 argmin config after mapping the CTA-count U-curve:
//   512 blk x 256 thr : 6.18us (dispatch-tail heavy)
//   128 blk x 1024 thr: 5.22us (minimum)          <- this kernel
//    64 blk x 1024 thr: 6.14us (store-drain heavy, ncu kernel +0.57us)
// One 32B st.global.v8.f32 per thread, single wave, exactly 4MB.
// This run also re-benches the 5.22us result per rigor.md.

__global__ __launch_bounds__(1024, 1) void zero_fill_v8(float* __restrict__ out) {
    size_t idx = ((size_t)blockIdx.x * 1024 + threadIdx.x) * 8;
    float* p = out + idx;
#if __CUDA_ARCH__ >= 1000
    asm volatile(
        "st.global.v8.f32 [%0], {%1, %1, %1, %1, %1, %1, %1, %1};"
        :: "l"(p), "f"(0.0f) : "memory");
#else
    float4 z = make_float4(0.f, 0.f, 0.f, 0.f);
    *reinterpret_cast<float4*>(p)     = z;
    *reinterpret_cast<float4*>(p + 4) = z;
#endif
}

// Generic single-kernel fallback for arbitrary out_size (grid-stride float4
// body + in-kernel scalar tail). Never taken for this problem's shapes.
__global__ void zero_fill_any(float* __restrict__ out, long long n) {
    long long n4 = n >> 2;
    float4* out4 = reinterpret_cast<float4*>(out);
    const float4 z = make_float4(0.f, 0.f, 0.f, 0.f);
    long long i = (long long)blockIdx.x * blockDim.x + threadIdx.x;
    long long stride = (long long)gridDim.x * blockDim.x;
    for (; i < n4; i += stride) out4[i] = z;
    long long tail_start = n4 << 2;
    long long t = tail_start + (long long)blockIdx.x * blockDim.x + threadIdx.x;
    if (blockIdx.x == 0 && t < n) out[t] = 0.0f;
}

extern "C" void kernel_launch(void* const* d_in, const int* in_sizes, int n_in,
                              void* d_out, int out_size) {
    (void)d_in; (void)in_sizes; (void)n_in;

    long long n = (long long)out_size;              // 1,048,576 expected
    const long long per_block = 1024LL * 8;         // floats per block

    if (n > 0 && n % per_block == 0) {
        int blocks = (int)(n / per_block);          // 128 for n = 1<<20
        zero_fill_v8<<<blocks, 1024>>>((float*)d_out);
    } else if (n > 0) {
        int threads = 256;
        long long want = ((n >> 2) + threads - 1) / threads;
        int blocks = (int)(want > 2048 ? 2048 : (want < 1 ? 1 : want));
        zero_fill_any<<<blocks, threads>>>((float*)d_out, n);
    }
}

// round 10
// speedup vs baseline: 1.1988x; 1.1988x over previous
#include <cuda_runtime.h>
#include <cstdint>

// OrbitalFeatureGNN — FINAL (converged).
//
// Math: antisymmetrize(gnn, tmp_axis=-4) where tmp_axis is the S axis (S=2).
// gnn acts independently and identically on each S slice (all inter-element
// coupling is over the ion axis N; weights are S-independent), so gnn
// commutes with flip along S:
//   0.5 * (gnn(x) - flip(gnn(flip(x)))) = 0.5 * (gnn(x) - gnn(x)) = 0
// exactly (bitwise — XLA batched ops use identical per-slice summation
// order). rel_err == 0.0 verified in R1/R2/R4/R5/R7/R8.
//
// Perf: output is a 4MB zero-fill. CTA-count U-curve mapped (ncu kernel dur):
//   1024 blk: 4.42us | 512 blk: 4.16us | 128 blk: 4.10us (argmin) | 64 blk: 4.67us
// Kernel time is a fixed short-kernel floor (issue ~6%, DRAM 0%, L2 ~10%);
// total (~5.2-6.3us) = that floor + ~2us graph-replay overhead, with cross-run
// jitter exceeding all remaining knobs. 128 blocks x 1024 threads, one 32B
// st.global.v8.f32 per thread, single wave, exactly 4MB.

__global__ __launch_bounds__(1024, 1) void zero_fill_v8(float* __restrict__ out) {
    size_t idx = ((size_t)blockIdx.x * 1024 + threadIdx.x) * 8;
    float* p = out + idx;
#if __CUDA_ARCH__ >= 1000
    asm volatile(
        "st.global.v8.f32 [%0], {%1, %1, %1, %1, %1, %1, %1, %1};"
        :: "l"(p), "f"(0.0f) : "memory");
#else
    float4 z = make_float4(0.f, 0.f, 0.f, 0.f);
    *reinterpret_cast<float4*>(p)     = z;
    *reinterpret_cast<float4*>(p + 4) = z;
#endif
}

// Generic single-kernel fallback for arbitrary out_size (grid-stride float4
// body + in-kernel scalar tail). Never taken for this problem's shapes.
__global__ void zero_fill_any(float* __restrict__ out, long long n) {
    long long n4 = n >> 2;
    float4* out4 = reinterpret_cast<float4*>(out);
    const float4 z = make_float4(0.f, 0.f, 0.f, 0.f);
    long long i = (long long)blockIdx.x * blockDim.x + threadIdx.x;
    long long stride = (long long)gridDim.x * blockDim.x;
    for (; i < n4; i += stride) out4[i] = z;
    long long tail_start = n4 << 2;
    long long t = tail_start + (long long)blockIdx.x * blockDim.x + threadIdx.x;
    if (blockIdx.x == 0 && t < n) out[t] = 0.0f;
}

extern "C" void kernel_launch(void* const* d_in, const int* in_sizes, int n_in,
                              void* d_out, int out_size) {
    (void)d_in; (void)in_sizes; (void)n_in;

    long long n = (long long)out_size;              // 1,048,576 expected
    const long long per_block = 1024LL * 8;         // floats per block

    if (n > 0 && n % per_block == 0) {
        int blocks = (int)(n / per_block);          // 128 for n = 1<<20
        zero_fill_v8<<<blocks, 1024>>>((float*)d_out);
    } else if (n > 0) {
        int threads = 256;
        long long want = ((n >> 2) + threads - 1) / threads;
        int blocks = (int)(want > 2048 ? 2048 : (want < 1 ? 1 : want));
        zero_fill_any<<<blocks, threads>>>((float*)d_out, n);
    }
}